// round 6
// baseline (speedup 1.0000x reference)
#include <cuda_runtime.h>
#include <cstdint>

// Problem constants (fixed shapes for this problem instance)
#define N_MASKS 128
#define HM 28
#define WM 28
#define IMG_H 800
#define IMG_W 1280
#define IN_W 1184.0f
#define IN_H 736.0f
#define ROWS_PER_BLOCK 8
#define PX_PER_THREAD 8
#define THREADS_PER_BLOCK (IMG_W / PX_PER_THREAD)   // 160

// 256-bit streaming store (Blackwell sm_100+). addr must be 32B-aligned.
__device__ __forceinline__ void stg_cs_v8(float* ptr, const float v[8]) {
#if __CUDA_ARCH__ >= 1000
    asm volatile(
        "st.global.cs.v8.f32 [%0], {%1, %2, %3, %4, %5, %6, %7, %8};"
        :: "l"(ptr),
           "f"(v[0]), "f"(v[1]), "f"(v[2]), "f"(v[3]),
           "f"(v[4]), "f"(v[5]), "f"(v[6]), "f"(v[7])
        : "memory");
#else
    float4 a = make_float4(v[0], v[1], v[2], v[3]);
    float4 b = make_float4(v[4], v[5], v[6], v[7]);
    __stcs(reinterpret_cast<float4*>(ptr), a);
    __stcs(reinterpret_cast<float4*>(ptr) + 1, b);
#endif
}

// Block = 8 consecutive rows of one mask. 160 threads, thread t owns pixels
// [8t, 8t+7] in each of the 8 rows -> 8x STG.256 per thread. Per-mask affine
// params are recomputed in-block from boxes (no separate prologue kernel).
__global__ void __launch_bounds__(THREADS_PER_BLOCK)
paste_kernel(const float* __restrict__ masks,
             const float* __restrict__ boxes,
             float* __restrict__ out) {
    const int n  = blockIdx.y;
    const int y0 = blockIdx.x * ROWS_PER_BLOCK;
    const int x8 = threadIdx.x * PX_PER_THREAD;

    // ---- per-mask affine params (redundant per thread; boxes hit L1) ----
    const float sx = (float)IMG_W / IN_W;
    const float sy = (float)IMG_H / IN_H;
    float bx0 = fminf(fmaxf(__ldg(boxes + 4 * n + 0) * sx, 0.0f), (float)IMG_W);
    float by0 = fminf(fmaxf(__ldg(boxes + 4 * n + 1) * sy, 0.0f), (float)IMG_H);
    float bx1 = fminf(fmaxf(__ldg(boxes + 4 * n + 2) * sx, 0.0f), (float)IMG_W);
    float by1 = fminf(fmaxf(__ldg(boxes + 4 * n + 3) * sy, 0.0f), (float)IMG_H);
    float ax = (float)WM / (bx1 - bx0);
    float ay = (float)HM / (by1 - by0);
    float bx = -bx0 * ax - 0.5f;
    float by = -by0 * ay - 0.5f;

    float* dst = out + ((size_t)n * IMG_H + y0) * IMG_W + x8;

    // Support tests (ax, ay > 0 so coords are monotone across the tile)
    float py0 = ay * ((float)y0 + 0.5f) + by;
    float pyL = py0 + (float)(ROWS_PER_BLOCK - 1) * ay;
    float px0 = ax * ((float)x8 + 0.5f) + bx;
    float pxL = px0 + (float)(PX_PER_THREAD - 1) * ax;
    bool active = (pyL > -1.0f) & (py0 < (float)HM) &
                  (pxL > -1.0f) & (px0 < (float)WM);

    if (!active) {
        const float z[8] = {0.f, 0.f, 0.f, 0.f, 0.f, 0.f, 0.f, 0.f};
#pragma unroll
        for (int r = 0; r < ROWS_PER_BLOCK; r++)
            stg_cs_v8(dst + (size_t)r * IMG_W, z);
        return;
    }

    // ---- horizontal precompute (shared by all 8 rows) ----
    int   ix0[PX_PER_THREAD], ix1[PX_PER_THREAD];
    float w0[PX_PER_THREAD], w1[PX_PER_THREAD];
#pragma unroll
    for (int k = 0; k < PX_PER_THREAD; k++) {
        float px  = px0 + (float)k * ax;
        float fx  = floorf(px);
        int   ix  = (int)fx;
        float wx1 = px - fx;
        float wx0 = 1.0f - wx1;
        bool inr = (px > -1.0f) & (px < (float)WM);
        bool vx0 = inr & (ix >= 0);
        bool vx1 = inr & (ix + 1 < WM);
        w0[k]  = vx0 ? wx0 : 0.0f;
        w1[k]  = vx1 ? wx1 : 0.0f;
        ix0[k] = min(max(ix, 0), WM - 1);
        ix1[k] = min(max(ix + 1, 0), WM - 1);
    }

    const float* mbase = masks + (size_t)n * (HM * WM);

#pragma unroll
    for (int r = 0; r < ROWS_PER_BLOCK; r++) {
        float py  = py0 + (float)r * ay;
        float fy  = floorf(py);
        int   iy  = (int)fy;
        float wy1 = py - fy;
        float wy0 = 1.0f - wy1;
        bool inr = (py > -1.0f) & (py < (float)HM);
        float wr0 = (inr & (iy >= 0))     ? wy0 : 0.0f;
        float wr1 = (inr & (iy + 1 < HM)) ? wy1 : 0.0f;
        const float* r0 = mbase + min(max(iy, 0), HM - 1) * WM;
        const float* r1 = mbase + min(max(iy + 1, 0), HM - 1) * WM;

        float res[PX_PER_THREAD];
#pragma unroll
        for (int k = 0; k < PX_PER_THREAD; k++) {
            float top = w0[k] * __ldg(r0 + ix0[k]) + w1[k] * __ldg(r0 + ix1[k]);
            float bot = w0[k] * __ldg(r1 + ix0[k]) + w1[k] * __ldg(r1 + ix1[k]);
            res[k] = wr0 * top + wr1 * bot;
        }
        stg_cs_v8(dst + (size_t)r * IMG_W, res);
    }
}

extern "C" void kernel_launch(void* const* d_in, const int* in_sizes, int n_in,
                              void* d_out, int out_size) {
    const float* masks = (const float*)d_in[0];
    const float* boxes = (const float*)d_in[1];
    float* out = (float*)d_out;

    dim3 grid(IMG_H / ROWS_PER_BLOCK, N_MASKS);   // (100, 128)
    paste_kernel<<<grid, THREADS_PER_BLOCK>>>(masks, boxes, out);
}